// round 16
// baseline (speedup 1.0000x reference)
#include <cuda_runtime.h>
#include <cuda_bf16.h>
#include <math.h>
#include <stdint.h>

#define BSZ 1024
#define LL  128
#define EE  256
#define HH  512
#define TT  20
#define G4  (4*HH)    // 2048
#define XW  (EE+HH)   // 768
#define VMAX 1024

// ---------------- persistent scratch ----------------------------------------
__device__ float g_C[BSZ*HH];
__device__ float g_PQ[BSZ*EE];
__device__ float g_GATT[BSZ*G4];
__device__ float g_WqT[HH*EE];
__device__ float g_WihT[EE*G4];
__device__ float g_WcT[XW*HH];
__device__ float g_WhhT[HH*G4];
__device__ float g_ProjEmb[VMAX*G4];
__device__ float g_BiasC[G4];
__device__ __nv_bfloat16 g_Xhi[BSZ*XW];    // [applied | h] split-bf16
__device__ __nv_bfloat16 g_Xlo[BSZ*XW];
__device__ __nv_bfloat16 g_Whi[XW*G4];     // Wcomb split, [K,N]
__device__ __nv_bfloat16 g_Wlo[XW*G4];
__device__ __nv_bfloat16 g_WqThi[HH*EE];
__device__ __nv_bfloat16 g_WqTlo[HH*EE];

__device__ __forceinline__ uint32_t smem_u32(const void* p) {
    return (uint32_t)__cvta_generic_to_shared(p);
}
#define CP16(dst, src) asm volatile("cp.async.cg.shared.global [%0], [%1], 16;\n" :: "r"(dst), "l"(src))

// ---------------- prep: 4 transposes + biascomb + init + zerotail (1 launch) --
__device__ __forceinline__ void transpose_dev(const float* __restrict__ in,
                                              float* __restrict__ out,
                                              int rows, int cols)
{
    __shared__ float tile[32][33];
    int x0 = blockIdx.x * 32, y0 = blockIdx.y * 32;
    if (x0 >= cols || y0 >= rows) return;
    int tx = threadIdx.x;
    for (int j = threadIdx.y; j < 32; j += 8) {
        int r = y0 + j, c = x0 + tx;
        if (r < rows && c < cols) tile[j][tx] = in[(size_t)r * cols + c];
    }
    __syncthreads();
    for (int j = threadIdx.y; j < 32; j += 8) {
        int orow = x0 + j, ocol = y0 + tx;
        if (orow < cols && ocol < rows) out[(size_t)orow * rows + ocol] = tile[tx][j];
    }
}

__global__ void prep_k(const float* __restrict__ Wq, const float* __restrict__ W_ih,
                       const float* __restrict__ Wc, const float* __restrict__ W_hh,
                       const float* __restrict__ b_ih, const float* __restrict__ b_hh,
                       const float* __restrict__ bc, const float* __restrict__ bq,
                       float* __restrict__ out, int ntail)
{
    int z = blockIdx.z;
    if (z == 0)      { transpose_dev(Wq,   g_WqT,  EE, HH); return; }
    else if (z == 1) { transpose_dev(W_ih, g_WihT, G4, EE); return; }
    else if (z == 2) { transpose_dev(Wc,   g_WcT,  HH, XW); return; }
    else if (z == 3) { transpose_dev(W_hh, g_WhhT, G4, HH); return; }

    const int tid  = threadIdx.y * 32 + threadIdx.x;
    const int lane = tid & 31, warp = tid >> 5;
    const int nb   = gridDim.x * gridDim.y;
    const int bid  = blockIdx.y * gridDim.x + blockIdx.x;

    for (int j = bid * 8 + warp; j < G4; j += nb * 8) {
        float s = 0.f;
        for (int h = lane; h < HH; h += 32) s += bc[h] * W_hh[(size_t)j * HH + h];
        #pragma unroll
        for (int o = 16; o; o >>= 1) s += __shfl_xor_sync(0xffffffffu, s, o);
        if (lane == 0) g_BiasC[j] = b_ih[j] + b_hh[j] + s;
    }
    for (int i = bid * 256 + tid; i < BSZ * HH; i += nb * 256) {
        g_C[i] = 0.f;
        int b = i >> 9, j = i & (HH - 1);
        g_Xhi[(size_t)b * XW + EE + j] = __float2bfloat16(0.f);
        g_Xlo[(size_t)b * XW + EE + j] = __float2bfloat16(0.f);
    }
    for (int i = bid * 256 + tid; i < BSZ * EE; i += nb * 256)
        g_PQ[i] = bq[i & (EE - 1)];
    for (int i = bid * 256 + tid; i < ntail; i += nb * 256)
        out[BSZ * LL + i] = 0.f;
}

// ---------------- setup GEMMs (z-sliced, zbase selects work) -------------------
__device__ __forceinline__ void gemm_dev(
    const float* __restrict__ A, const float* __restrict__ B,
    float* __restrict__ C, __nv_bfloat16* __restrict__ Chi,
    __nv_bfloat16* __restrict__ Clo,
    int M, int N, int K, int lda, int ldb, int ldc, int mode)
{
    __shared__ float As[16][68];
    __shared__ float Bs[16][68];
    const int tid = threadIdx.x;
    const int tx  = tid & 15, ty = tid >> 4;
    const int bm  = blockIdx.y << 6, bn = blockIdx.x << 6;
    const int arow = tid >> 2, ak = (tid & 3) << 2;
    const int brow = tid >> 4, bcol = (tid & 15) << 2;

    float acc[4][4];
    #pragma unroll
    for (int i = 0; i < 4; i++)
        #pragma unroll
        for (int j = 0; j < 4; j++) acc[i][j] = 0.f;

    const bool aval = (bm + arow) < M;
    const float* Aptr = A + (size_t)(bm + arow) * lda + ak;
    const float* Bptr = B + (size_t)brow * ldb + bn + bcol;

    for (int k0 = 0; k0 < K; k0 += 16) {
        float4 av = aval ? *(const float4*)(Aptr + k0)
                         : make_float4(0.f, 0.f, 0.f, 0.f);
        As[ak + 0][arow] = av.x; As[ak + 1][arow] = av.y;
        As[ak + 2][arow] = av.z; As[ak + 3][arow] = av.w;
        float4 bv = *(const float4*)(Bptr + (size_t)k0 * ldb);
        *(float4*)(&Bs[brow][bcol]) = bv;
        __syncthreads();
        #pragma unroll
        for (int k = 0; k < 16; k++) {
            float4 a = *(const float4*)(&As[k][ty << 2]);
            float4 b = *(const float4*)(&Bs[k][tx << 2]);
            acc[0][0] += a.x * b.x; acc[0][1] += a.x * b.y; acc[0][2] += a.x * b.z; acc[0][3] += a.x * b.w;
            acc[1][0] += a.y * b.x; acc[1][1] += a.y * b.y; acc[1][2] += a.y * b.z; acc[1][3] += a.y * b.w;
            acc[2][0] += a.z * b.x; acc[2][1] += a.z * b.y; acc[2][2] += a.z * b.z; acc[2][3] += a.z * b.w;
            acc[3][0] += a.w * b.x; acc[3][1] += a.w * b.y; acc[3][2] += a.w * b.z; acc[3][3] += a.w * b.w;
        }
        __syncthreads();
    }

    #pragma unroll
    for (int i = 0; i < 4; i++) {
        int row = bm + (ty << 2) + i;
        if (row < M) {
            if (mode == 0) {
                *(float4*)(C + (size_t)row * ldc + bn + (tx << 2)) =
                    make_float4(acc[i][0], acc[i][1], acc[i][2], acc[i][3]);
            } else {
                #pragma unroll
                for (int q = 0; q < 4; q++) {
                    float o = acc[i][q];
                    __nv_bfloat16 h = __float2bfloat16(o);
                    size_t off = (size_t)row * ldc + bn + (tx << 2) + q;
                    Chi[off] = h;
                    Clo[off] = __float2bfloat16(o - __bfloat162float(h));
                }
            }
        }
    }
}

__global__ __launch_bounds__(256) void gemm2_k(const float* __restrict__ emb,
                                               int Vp1, int zbase)
{
    int z = blockIdx.z + zbase;
    if (z == 0) {
        if (blockIdx.y < 12)
            gemm_dev(g_WcT, g_WhhT, nullptr, g_Whi, g_Wlo,
                     XW, G4, HH, HH, G4, G4, 1);
    } else if (z == 1) {
        gemm_dev(emb, g_WihT, g_ProjEmb, nullptr, nullptr,
                 Vp1, G4, EE, EE, G4, G4, 0);
    } else {
        int bid = blockIdx.y * gridDim.x + blockIdx.x;
        int i = bid * 256 + threadIdx.x;
        if (i < HH * EE) {
            float x = g_WqT[i];
            __nv_bfloat16 h = __float2bfloat16(x);
            g_WqThi[i] = h;
            g_WqTlo[i] = __float2bfloat16(x - __bfloat162float(h));
        }
    }
}

// ---------------- MMA helpers --------------------------------------------------
__device__ __forceinline__ void ldsm_x4(uint32_t r[4], uint32_t addr) {
    asm volatile("ldmatrix.sync.aligned.m8n8.x4.shared.b16 {%0,%1,%2,%3}, [%4];\n"
        : "=r"(r[0]), "=r"(r[1]), "=r"(r[2]), "=r"(r[3]) : "r"(addr));
}
__device__ __forceinline__ void ldsm_x2t(uint32_t r[2], uint32_t addr) {
    asm volatile("ldmatrix.sync.aligned.m8n8.x2.trans.shared.b16 {%0,%1}, [%2];\n"
        : "=r"(r[0]), "=r"(r[1]) : "r"(addr));
}
__device__ __forceinline__ void mma16816(float* c, const uint32_t a[4], const uint32_t b[2]) {
    asm volatile(
        "mma.sync.aligned.m16n8k16.row.col.f32.bf16.bf16.f32 "
        "{%0,%1,%2,%3}, {%4,%5,%6,%7}, {%8,%9}, {%0,%1,%2,%3};\n"
        : "+f"(c[0]), "+f"(c[1]), "+f"(c[2]), "+f"(c[3])
        : "r"(a[0]), "r"(a[1]), "r"(a[2]), "r"(a[3]), "r"(b[0]), "r"(b[1]));
}

// ---------------- gates GEMM (128x128x32, 16 warps, 3-stage) ------------------
#define MM_SA 40
#define MM_SB 136
#define MM_BM 128
#define MM_BN 128
#define MM_BK 32
#define MM_ASZ (MM_BM*MM_SA)
#define MM_BSZ (MM_BK*MM_SB)
#define MM_STG (2*MM_ASZ + 2*MM_BSZ)   // 18944 elems
#define MM_NST 3
#define MM_SMEM (MM_NST*MM_STG*2)      // 113664 B

__global__ __launch_bounds__(512, 1) void mma_gemm_k(
    const __nv_bfloat16* __restrict__ Ahi, const __nv_bfloat16* __restrict__ Alo,
    const __nv_bfloat16* __restrict__ Bhi, const __nv_bfloat16* __restrict__ Blo,
    float* __restrict__ C, const int* __restrict__ msg, int t)
{
    extern __shared__ __nv_bfloat16 sm[];
    __nv_bfloat16* stg[MM_NST] = { sm, sm + MM_STG, sm + 2 * MM_STG };

    const int tid  = threadIdx.x;
    const int lane = tid & 31, warp = tid >> 5;
    const int bm = blockIdx.y * MM_BM, bn = blockIdx.x * MM_BN;
    const int wm = (warp >> 2) * 32, wn = (warp & 3) * 32;   // 32x32 warp tile

    float acc[2][4][4];
    #pragma unroll
    for (int i = 0; i < 2; i++)
        #pragma unroll
        for (int j = 0; j < 4; j++)
            #pragma unroll
            for (int l = 0; l < 4; l++) acc[i][j][l] = 0.f;

    auto issue_loads = [&](int s, int k0) {
        __nv_bfloat16* sAhi = stg[s];
        __nv_bfloat16* sAlo = stg[s] + MM_ASZ;
        __nv_bfloat16* sBhi = stg[s] + 2 * MM_ASZ;
        __nv_bfloat16* sBlo = stg[s] + 2 * MM_ASZ + MM_BSZ;
        int ar = tid >> 2, ac = (tid & 3) * 8;
        CP16(smem_u32(sAhi + ar * MM_SA + ac), Ahi + (size_t)(bm + ar) * XW + k0 + ac);
        CP16(smem_u32(sAlo + ar * MM_SA + ac), Alo + (size_t)(bm + ar) * XW + k0 + ac);
        int br = tid >> 4, bc = (tid & 15) * 8;
        CP16(smem_u32(sBhi + br * MM_SB + bc), Bhi + (size_t)(k0 + br) * G4 + bn + bc);
        CP16(smem_u32(sBlo + br * MM_SB + bc), Blo + (size_t)(k0 + br) * G4 + bn + bc);
        asm volatile("cp.async.commit_group;\n");
    };

    const int niter = XW / MM_BK;   // 24
    issue_loads(0, 0);
    issue_loads(1, MM_BK);

    const int a_ro = (lane & 7) + ((lane >> 3) & 1) * 8;
    const int a_ko = ((lane >> 4) & 1) * 8;
    const int b_ro = (lane & 7) + ((lane >> 3) & 1) * 8;

    for (int it = 0; it < niter; it++) {
        if (it + 2 < niter) { issue_loads((it + 2) % MM_NST, (it + 2) * MM_BK);
                              asm volatile("cp.async.wait_group 2;\n"); }
        else if (it + 1 < niter) asm volatile("cp.async.wait_group 1;\n");
        else                     asm volatile("cp.async.wait_group 0;\n");
        __syncthreads();

        const int s = it % MM_NST;
        const __nv_bfloat16* sAhi = stg[s];
        const __nv_bfloat16* sAlo = stg[s] + MM_ASZ;
        const __nv_bfloat16* sBhi = stg[s] + 2 * MM_ASZ;
        const __nv_bfloat16* sBlo = stg[s] + 2 * MM_ASZ + MM_BSZ;

        #pragma unroll
        for (int ks = 0; ks < MM_BK; ks += 16) {
            uint32_t bh[4][2], bl[4][2];
            #pragma unroll
            for (int nf = 0; nf < 4; nf++) {
                ldsm_x2t(bh[nf], smem_u32(sBhi + (ks + b_ro) * MM_SB + wn + nf * 8));
                ldsm_x2t(bl[nf], smem_u32(sBlo + (ks + b_ro) * MM_SB + wn + nf * 8));
            }
            uint32_t ah[2][4], al[2][4];
            #pragma unroll
            for (int mf = 0; mf < 2; mf++) {
                int arow = wm + mf * 16 + a_ro;
                ldsm_x4(ah[mf], smem_u32(sAhi + arow * MM_SA + ks + a_ko));
                ldsm_x4(al[mf], smem_u32(sAlo + arow * MM_SA + ks + a_ko));
            }
            #pragma unroll
            for (int mf = 0; mf < 2; mf++)
                #pragma unroll
                for (int nf = 0; nf < 4; nf++)
                    mma16816(acc[mf][nf], ah[mf], bh[nf]);
            #pragma unroll
            for (int mf = 0; mf < 2; mf++)
                #pragma unroll
                for (int nf = 0; nf < 4; nf++)
                    mma16816(acc[mf][nf], ah[mf], bl[nf]);
            #pragma unroll
            for (int mf = 0; mf < 2; mf++)
                #pragma unroll
                for (int nf = 0; nf < 4; nf++)
                    mma16816(acc[mf][nf], al[mf], bh[nf]);
        }
        __syncthreads();
    }

    // epilogue: GATT = acc + ProjEmb[tok] + BiasC
    #pragma unroll
    for (int mf = 0; mf < 2; mf++) {
        int row0 = bm + wm + mf * 16 + (lane >> 2);
        int tok0 = msg[row0 * TT + t];
        int tok1 = msg[(row0 + 8) * TT + t];
        const float* pe0 = g_ProjEmb + (size_t)tok0 * G4;
        const float* pe1 = g_ProjEmb + (size_t)tok1 * G4;
        #pragma unroll
        for (int nf = 0; nf < 4; nf++) {
            int col = bn + wn + nf * 8 + (lane & 3) * 2;
            float2 bi = *(const float2*)(g_BiasC + col);
            float2 p0 = *(const float2*)(pe0 + col);
            float2 p1 = *(const float2*)(pe1 + col);
            *(float2*)(C + (size_t)row0 * G4 + col) =
                make_float2((acc[mf][nf][0] + p0.x) + bi.x,
                            (acc[mf][nf][1] + p0.y) + bi.y);
            *(float2*)(C + (size_t)(row0 + 8) * G4 + col) =
                make_float2((acc[mf][nf][2] + p1.x) + bi.x,
                            (acc[mf][nf][3] + p1.y) + bi.y);
        }
    }
}

// ---------------- split-bf16 pq GEMM (64x64x32, 128 thr) ----------------------
#define P_SA 40
#define P_SB 72
#define P_BM 64
#define P_BN 64
#define P_BK 32
#define P_ASZ (P_BM*P_SA)
#define P_BSZ (P_BK*P_SB)
#define P_STG (2*P_ASZ + 2*P_BSZ)
#define P_SMEM (2*P_STG*2)

__global__ __launch_bounds__(128) void mma_pq_k(
    const __nv_bfloat16* __restrict__ Ahi, const __nv_bfloat16* __restrict__ Alo,
    const __nv_bfloat16* __restrict__ Bhi, const __nv_bfloat16* __restrict__ Blo,
    float* __restrict__ C, const float* __restrict__ bias,
    int M, int N, int K, int lda, int ldb, int ldc)
{
    extern __shared__ __nv_bfloat16 smb[];
    __nv_bfloat16* stg[2] = { smb, smb + P_STG };

    const int tid  = threadIdx.x;
    const int lane = tid & 31, warp = tid >> 5;
    const int bm = blockIdx.y * P_BM, bn = blockIdx.x * P_BN;
    const int wm = (warp >> 1) * 32, wn = (warp & 1) * 32;

    float acc[2][4][4];
    #pragma unroll
    for (int i = 0; i < 2; i++)
        #pragma unroll
        for (int j = 0; j < 4; j++)
            #pragma unroll
            for (int l = 0; l < 4; l++) acc[i][j][l] = 0.f;

    auto issue_loads = [&](int s, int k0) {
        __nv_bfloat16* sAhi = stg[s];
        __nv_bfloat16* sAlo = stg[s] + P_ASZ;
        __nv_bfloat16* sBhi = stg[s] + 2 * P_ASZ;
        __nv_bfloat16* sBlo = stg[s] + 2 * P_ASZ + P_BSZ;
        #pragma unroll
        for (int i = 0; i < 2; i++) {
            int ai = tid * 2 + i, ar = ai >> 2, ac = (ai & 3) * 8;
            CP16(smem_u32(sAhi + ar * P_SA + ac), Ahi + (size_t)(bm + ar) * lda + k0 + ac);
            CP16(smem_u32(sAlo + ar * P_SA + ac), Alo + (size_t)(bm + ar) * lda + k0 + ac);
            int bi = tid * 2 + i, br = bi >> 3, bc = (bi & 7) * 8;
            CP16(smem_u32(sBhi + br * P_SB + bc), Bhi + (size_t)(k0 + br) * ldb + bn + bc);
            CP16(smem_u32(sBlo + br * P_SB + bc), Blo + (size_t)(k0 + br) * ldb + bn + bc);
        }
        asm volatile("cp.async.commit_group;\n");
    };

    const int niter = K / P_BK;
    issue_loads(0, 0);

    const int a_ro = (lane & 7) + ((lane >> 3) & 1) * 8;
    const int a_ko = ((lane >> 4) & 1) * 8;
    const int b_ro = (lane & 7) + ((lane >> 3) & 1) * 8;

    for (int it = 0; it < niter; it++) {
        int s = it & 1;
        if (it + 1 < niter) { issue_loads(s ^ 1, (it + 1) * P_BK);
                              asm volatile("cp.async.wait_group 1;\n"); }
        else                  asm volatile("cp.async.wait_group 0;\n");
        __syncthreads();

        const __nv_bfloat16* sAhi = stg[s];
        const __nv_bfloat16* sAlo = stg[s] + P_ASZ;
        const __nv_bfloat16* sBhi = stg[s] + 2 * P_ASZ;
        const __nv_bfloat16* sBlo = stg[s] + 2 * P_ASZ + P_BSZ;

        #pragma unroll
        for (int ks = 0; ks < P_BK; ks += 16) {
            uint32_t bh[4][2], bl[4][2];
            #pragma unroll
            for (int nf = 0; nf < 4; nf++) {
                ldsm_x2t(bh[nf], smem_u32(sBhi + (ks + b_ro) * P_SB + wn + nf * 8));
                ldsm_x2t(bl[nf], smem_u32(sBlo + (ks + b_ro) * P_SB + wn + nf * 8));
            }
            uint32_t ah[2][4], al[2][4];
            #pragma unroll
            for (int mf = 0; mf < 2; mf++) {
                int arow = wm + mf * 16 + a_ro;
                ldsm_x4(ah[mf], smem_u32(sAhi + arow * P_SA + ks + a_ko));
                ldsm_x4(al[mf], smem_u32(sAlo + arow * P_SA + ks + a_ko));
            }
            #pragma unroll
            for (int mf = 0; mf < 2; mf++)
                #pragma unroll
                for (int nf = 0; nf < 4; nf++)
                    mma16816(acc[mf][nf], ah[mf], bh[nf]);
            #pragma unroll
            for (int mf = 0; mf < 2; mf++)
                #pragma unroll
                for (int nf = 0; nf < 4; nf++)
                    mma16816(acc[mf][nf], ah[mf], bl[nf]);
            #pragma unroll
            for (int mf = 0; mf < 2; mf++)
                #pragma unroll
                for (int nf = 0; nf < 4; nf++)
                    mma16816(acc[mf][nf], al[mf], bh[nf]);
        }
        __syncthreads();
    }

    #pragma unroll
    for (int mf = 0; mf < 2; mf++) {
        int row0 = bm + wm + mf * 16 + (lane >> 2);
        #pragma unroll
        for (int nf = 0; nf < 4; nf++) {
            int col = bn + wn + nf * 8 + (lane & 3) * 2;
            float b0 = bias[col], b1 = bias[col + 1];
            *(float2*)(C + (size_t)row0 * ldc + col) =
                make_float2(acc[mf][nf][0] + b0, acc[mf][nf][1] + b1);
            *(float2*)(C + (size_t)(row0 + 8) * ldc + col) =
                make_float2(acc[mf][nf][2] + b0, acc[mf][nf][3] + b1);
        }
    }
}

// ---------------- flash attend: 2-stage, issue-first, register-cached pq ------
#define FA_CH 8
#define FA_NCH (LL/FA_CH)
#define FA_SMEM ((2*FA_CH*EE + LL + FA_CH + FA_CH + 8) * 4)

__global__ __launch_bounds__(256, 6) void attend_flash_k(
    const float* __restrict__ Mg, const int* __restrict__ mask,
    const int* __restrict__ lengths, float* __restrict__ out, int t)
{
    extern __shared__ float smf[];
    float* bufs[2] = { smf, smf + FA_CH * EE };
    float* smSall = smf + 2 * FA_CH * EE;
    float* smS8   = smSall + LL;
    float* smE    = smS8 + FA_CH;
    float* smMisc = smE + FA_CH;

    const int b = blockIdx.x, tid = threadIdx.x;
    const int warp = tid >> 5, lane = tid & 31;

    // pq slice cached in registers: score loop uses indices (lane + j*32),
    // identical every chunk and warp. Coalesced global load, done once.
    float pqr[8];
    #pragma unroll
    for (int j = 0; j < 8; j++) pqr[j] = g_PQ[b * EE + lane + j * 32];

    const float* gM = Mg + (size_t)b * LL * EE;

    auto issue = [&](int c) {
        float* dst = bufs[c & 1];
        const float* src = gM + c * FA_CH * EE;
        #pragma unroll
        for (int i = 0; i < 2; i++) {
            int ch = tid + i * 256;
            CP16(smem_u32(dst + ch * 4), src + ch * 4);
        }
        asm volatile("cp.async.commit_group;\n");
    };

    issue(0);

    float a = 0.f;
    float m = -1e30f, d = 0.f;

    for (int c = 0; c < FA_NCH; c++) {
        if (c + 1 < FA_NCH) { issue(c + 1); asm volatile("cp.async.wait_group 1;\n"); }
        else                  asm volatile("cp.async.wait_group 0;\n");
        __syncthreads();
        float* smM = bufs[c & 1];

        {   // one row per warp (8 rows, 8 warps)
            int l = warp;
            float s = 0.f;
            #pragma unroll
            for (int j = 0; j < EE / 32; j++)
                s += smM[l * EE + lane + j * 32] * pqr[j];
            #pragma unroll
            for (int o = 16; o; o >>= 1) s += __shfl_xor_sync(0xffffffffu, s, o);
            if (lane == 0) {
                int gl = c * FA_CH + l;
                float sv = (mask[b * LL + gl] != 0) ? -1e30f : s;
                smS8[l] = sv;
                smSall[gl] = sv;
            }
        }
        __syncthreads();

        if (warp == 0) {
            float sl = (lane < FA_CH) ? smS8[lane] : -1e30f;
            float mc = sl;
            #pragma unroll
            for (int o = 16; o; o >>= 1) mc = fmaxf(mc, __shfl_xor_sync(0xffffffffu, mc, o));
            float m_new = fmaxf(m, mc);
            float scale = expf(m - m_new);
            float e = (lane < FA_CH) ? expf(sl - m_new) : 0.f;
            float esum = e;
            #pragma unroll
            for (int o = 16; o; o >>= 1) esum += __shfl_xor_sync(0xffffffffu, esum, o);
            d = d * scale + esum;
            m = m_new;
            if (lane < FA_CH) smE[lane] = e;
            if (lane == 0) smMisc[0] = scale;
        }
        __syncthreads();

        float sc = smMisc[0];
        a *= sc;
        #pragma unroll
        for (int l = 0; l < FA_CH; l++)
            a += smE[l] * smM[l * EE + tid];
        __syncthreads();
    }

    if (warp == 0 && lane == 0) { smMisc[1] = m; smMisc[2] = 1.f / d; }
    __syncthreads();
    float m_fin = smMisc[1], inv_d = smMisc[2];

    float app = a * inv_d;
    __nv_bfloat16 h = __float2bfloat16(app);
    g_Xhi[(size_t)b * XW + tid] = h;
    g_Xlo[(size_t)b * XW + tid] = __float2bfloat16(app - __bfloat162float(h));

    if (tid < LL) {
        int len = lengths[b];
        len = min(max(len, 0), TT);
        if (len == t) out[(size_t)b * LL + tid] = expf(smSall[tid] - m_fin) * inv_d;
    }
}

// ---------------- LSTM cell (gates pre-summed in GATT) ------------------------
__global__ void lstm_k(int dummy)
{
    int idx = blockIdx.x * blockDim.x + threadIdx.x;
    int b = idx >> 9, j = idx & (HH - 1);
    const float* ga = g_GATT + (size_t)b * G4;
    float gi = ga[j];
    float gf = ga[HH + j];
    float gg = ga[2 * HH + j];
    float go = ga[3 * HH + j];
    float c  = g_C[idx];
    float si = 1.f / (1.f + expf(-gi));
    float sf = 1.f / (1.f + expf(-gf));
    float so = 1.f / (1.f + expf(-go));
    float cn = sf * c + si * tanhf(gg);
    float hn = so * tanhf(cn);
    g_C[idx] = cn;
    __nv_bfloat16 hb = __float2bfloat16(hn);
    g_Xhi[(size_t)b * XW + EE + j] = hb;
    g_Xlo[(size_t)b * XW + EE + j] = __float2bfloat16(hn - __bfloat162float(hb));
}

// ---------------- driver -----------------------------------------------------
extern "C" void kernel_launch(void* const* d_in, const int* in_sizes, int n_in,
                              void* d_out, int out_size)
{
    const int*   msg     = (const int*)d_in[0];
    const float* Mg      = (const float*)d_in[1];
    const int*   mask    = (const int*)d_in[2];
    const int*   lengths = (const int*)d_in[3];
    const float* emb     = (const float*)d_in[4];
    const float* Wq      = (const float*)d_in[5];
    const float* bq      = (const float*)d_in[6];
    const float* Wc      = (const float*)d_in[7];
    const float* bc      = (const float*)d_in[8];
    const float* W_ih    = (const float*)d_in[9];
    const float* W_hh    = (const float*)d_in[10];
    const float* b_ih    = (const float*)d_in[11];
    const float* b_hh    = (const float*)d_in[12];
    float* out = (float*)d_out;
    int Vp1 = in_sizes[4] / EE;
    if (Vp1 > VMAX) Vp1 = VMAX;
    int ntail = out_size - BSZ * LL;
    if (ntail < 0) ntail = 0;

    float *pPQ, *pGATT;
    __nv_bfloat16 *pXhi, *pXlo, *pWhi, *pWlo, *pWqThi, *pWqTlo;
    cudaGetSymbolAddress((void**)&pPQ,    g_PQ);
    cudaGetSymbolAddress((void**)&pGATT,  g_GATT);
    cudaGetSymbolAddress((void**)&pXhi,   g_Xhi);
    cudaGetSymbolAddress((void**)&pXlo,   g_Xlo);
    cudaGetSymbolAddress((void**)&pWhi,   g_Whi);
    cudaGetSymbolAddress((void**)&pWlo,   g_Wlo);
    cudaGetSymbolAddress((void**)&pWqThi, g_WqThi);
    cudaGetSymbolAddress((void**)&pWqTlo, g_WqTlo);

    cudaFuncSetAttribute(attend_flash_k, cudaFuncAttributeMaxDynamicSharedMemorySize, FA_SMEM);
    cudaFuncSetAttribute(mma_gemm_k, cudaFuncAttributeMaxDynamicSharedMemorySize, MM_SMEM);
    cudaFuncSetAttribute(mma_pq_k,   cudaFuncAttributeMaxDynamicSharedMemorySize, P_SMEM);

    // setup launches
    prep_k<<<dim3(24, 64, 5), dim3(32, 8)>>>(Wq, W_ih, Wc, W_hh,
                                             b_ih, b_hh, bc, bq, out, ntail);
    gemm2_k<<<dim3(32, 16, 1), 256>>>(emb, Vp1, 0);   // Wcomb split
    gemm2_k<<<dim3(32, 16, 2), 256>>>(emb, Vp1, 1);   // ProjEmb + WqT split

    for (int t = 0; t < TT; t++) {
        attend_flash_k<<<BSZ, 256, FA_SMEM>>>(Mg, mask, lengths, out, t);
        mma_gemm_k<<<dim3(G4 / MM_BN, BSZ / MM_BM), 512, MM_SMEM>>>(
            pXhi, pXlo, pWhi, pWlo, pGATT, msg, t);
        lstm_k<<<(BSZ * HH) / 256, 256>>>(0);
        mma_pq_k<<<dim3(EE / P_BN, BSZ / P_BM), 128, P_SMEM>>>(
            pXhi + EE, pXlo + EE, pWqThi, pWqTlo, pPQ, bq,
            BSZ, EE, HH, XW, EE, EE);
    }
    attend_flash_k<<<BSZ, 256, FA_SMEM>>>(Mg, mask, lengths, out, TT);
}

// round 17
// speedup vs baseline: 1.1143x; 1.1143x over previous
#include <cuda_runtime.h>
#include <cuda_bf16.h>
#include <math.h>
#include <stdint.h>

#define BSZ 1024
#define LL  128
#define EE  256
#define HH  512
#define TT  20
#define G4  (4*HH)    // 2048
#define XW  (EE+HH)   // 768
#define VMAX 1024

// ---------------- persistent scratch ----------------------------------------
__device__ float g_C[BSZ*HH];
__device__ float g_PQ[BSZ*EE];
__device__ float g_GATT[BSZ*G4];
__device__ float g_WqT[HH*EE];
__device__ float g_WihT[EE*G4];
__device__ float g_WcT[XW*HH];
__device__ float g_WhhT[HH*G4];
__device__ float g_ProjEmb[VMAX*G4];
__device__ float g_BiasC[G4];
__device__ __nv_bfloat16 g_Xhi[BSZ*XW];    // [applied | h] split-bf16
__device__ __nv_bfloat16 g_Xlo[BSZ*XW];
__device__ __nv_bfloat16 g_Whi[XW*G4];     // Wcomb split, [K,N]
__device__ __nv_bfloat16 g_Wlo[XW*G4];
__device__ __nv_bfloat16 g_WqThi[HH*EE];
__device__ __nv_bfloat16 g_WqTlo[HH*EE];

__device__ __forceinline__ uint32_t smem_u32(const void* p) {
    return (uint32_t)__cvta_generic_to_shared(p);
}
#define CP16(dst, src) asm volatile("cp.async.cg.shared.global [%0], [%1], 16;\n" :: "r"(dst), "l"(src))

// ---------------- prep: 4 transposes + biascomb + init + zerotail (1 launch) --
__device__ __forceinline__ void transpose_dev(const float* __restrict__ in,
                                              float* __restrict__ out,
                                              int rows, int cols)
{
    __shared__ float tile[32][33];
    int x0 = blockIdx.x * 32, y0 = blockIdx.y * 32;
    if (x0 >= cols || y0 >= rows) return;
    int tx = threadIdx.x;
    for (int j = threadIdx.y; j < 32; j += 8) {
        int r = y0 + j, c = x0 + tx;
        if (r < rows && c < cols) tile[j][tx] = in[(size_t)r * cols + c];
    }
    __syncthreads();
    for (int j = threadIdx.y; j < 32; j += 8) {
        int orow = x0 + j, ocol = y0 + tx;
        if (orow < cols && ocol < rows) out[(size_t)orow * rows + ocol] = tile[tx][j];
    }
}

__global__ void prep_k(const float* __restrict__ Wq, const float* __restrict__ W_ih,
                       const float* __restrict__ Wc, const float* __restrict__ W_hh,
                       const float* __restrict__ b_ih, const float* __restrict__ b_hh,
                       const float* __restrict__ bc, const float* __restrict__ bq,
                       float* __restrict__ out, int ntail)
{
    int z = blockIdx.z;
    if (z == 0)      { transpose_dev(Wq,   g_WqT,  EE, HH); return; }
    else if (z == 1) { transpose_dev(W_ih, g_WihT, G4, EE); return; }
    else if (z == 2) { transpose_dev(Wc,   g_WcT,  HH, XW); return; }
    else if (z == 3) { transpose_dev(W_hh, g_WhhT, G4, HH); return; }

    const int tid  = threadIdx.y * 32 + threadIdx.x;
    const int lane = tid & 31, warp = tid >> 5;
    const int nb   = gridDim.x * gridDim.y;
    const int bid  = blockIdx.y * gridDim.x + blockIdx.x;

    for (int j = bid * 8 + warp; j < G4; j += nb * 8) {
        float s = 0.f;
        for (int h = lane; h < HH; h += 32) s += bc[h] * W_hh[(size_t)j * HH + h];
        #pragma unroll
        for (int o = 16; o; o >>= 1) s += __shfl_xor_sync(0xffffffffu, s, o);
        if (lane == 0) g_BiasC[j] = b_ih[j] + b_hh[j] + s;
    }
    for (int i = bid * 256 + tid; i < BSZ * HH; i += nb * 256) {
        g_C[i] = 0.f;
        int b = i >> 9, j = i & (HH - 1);
        g_Xhi[(size_t)b * XW + EE + j] = __float2bfloat16(0.f);
        g_Xlo[(size_t)b * XW + EE + j] = __float2bfloat16(0.f);
    }
    for (int i = bid * 256 + tid; i < BSZ * EE; i += nb * 256)
        g_PQ[i] = bq[i & (EE - 1)];
    for (int i = bid * 256 + tid; i < ntail; i += nb * 256)
        out[BSZ * LL + i] = 0.f;
}

// ---------------- setup GEMMs (z-sliced, zbase selects work) -------------------
__device__ __forceinline__ void gemm_dev(
    const float* __restrict__ A, const float* __restrict__ B,
    float* __restrict__ C, __nv_bfloat16* __restrict__ Chi,
    __nv_bfloat16* __restrict__ Clo,
    int M, int N, int K, int lda, int ldb, int ldc, int mode)
{
    __shared__ float As[16][68];
    __shared__ float Bs[16][68];
    const int tid = threadIdx.x;
    const int tx  = tid & 15, ty = tid >> 4;
    const int bm  = blockIdx.y << 6, bn = blockIdx.x << 6;
    const int arow = tid >> 2, ak = (tid & 3) << 2;
    const int brow = tid >> 4, bcol = (tid & 15) << 2;

    float acc[4][4];
    #pragma unroll
    for (int i = 0; i < 4; i++)
        #pragma unroll
        for (int j = 0; j < 4; j++) acc[i][j] = 0.f;

    const bool aval = (bm + arow) < M;
    const float* Aptr = A + (size_t)(bm + arow) * lda + ak;
    const float* Bptr = B + (size_t)brow * ldb + bn + bcol;

    for (int k0 = 0; k0 < K; k0 += 16) {
        float4 av = aval ? *(const float4*)(Aptr + k0)
                         : make_float4(0.f, 0.f, 0.f, 0.f);
        As[ak + 0][arow] = av.x; As[ak + 1][arow] = av.y;
        As[ak + 2][arow] = av.z; As[ak + 3][arow] = av.w;
        float4 bv = *(const float4*)(Bptr + (size_t)k0 * ldb);
        *(float4*)(&Bs[brow][bcol]) = bv;
        __syncthreads();
        #pragma unroll
        for (int k = 0; k < 16; k++) {
            float4 a = *(const float4*)(&As[k][ty << 2]);
            float4 b = *(const float4*)(&Bs[k][tx << 2]);
            acc[0][0] += a.x * b.x; acc[0][1] += a.x * b.y; acc[0][2] += a.x * b.z; acc[0][3] += a.x * b.w;
            acc[1][0] += a.y * b.x; acc[1][1] += a.y * b.y; acc[1][2] += a.y * b.z; acc[1][3] += a.y * b.w;
            acc[2][0] += a.z * b.x; acc[2][1] += a.z * b.y; acc[2][2] += a.z * b.z; acc[2][3] += a.z * b.w;
            acc[3][0] += a.w * b.x; acc[3][1] += a.w * b.y; acc[3][2] += a.w * b.z; acc[3][3] += a.w * b.w;
        }
        __syncthreads();
    }

    #pragma unroll
    for (int i = 0; i < 4; i++) {
        int row = bm + (ty << 2) + i;
        if (row < M) {
            if (mode == 0) {
                *(float4*)(C + (size_t)row * ldc + bn + (tx << 2)) =
                    make_float4(acc[i][0], acc[i][1], acc[i][2], acc[i][3]);
            } else {
                #pragma unroll
                for (int q = 0; q < 4; q++) {
                    float o = acc[i][q];
                    __nv_bfloat16 h = __float2bfloat16(o);
                    size_t off = (size_t)row * ldc + bn + (tx << 2) + q;
                    Chi[off] = h;
                    Clo[off] = __float2bfloat16(o - __bfloat162float(h));
                }
            }
        }
    }
}

__global__ __launch_bounds__(256) void gemm2_k(const float* __restrict__ emb,
                                               int Vp1, int zbase)
{
    int z = blockIdx.z + zbase;
    if (z == 0) {
        if (blockIdx.y < 12)
            gemm_dev(g_WcT, g_WhhT, nullptr, g_Whi, g_Wlo,
                     XW, G4, HH, HH, G4, G4, 1);
    } else if (z == 1) {
        gemm_dev(emb, g_WihT, g_ProjEmb, nullptr, nullptr,
                 Vp1, G4, EE, EE, G4, G4, 0);
    } else {
        int bid = blockIdx.y * gridDim.x + blockIdx.x;
        int i = bid * 256 + threadIdx.x;
        if (i < HH * EE) {
            float x = g_WqT[i];
            __nv_bfloat16 h = __float2bfloat16(x);
            g_WqThi[i] = h;
            g_WqTlo[i] = __float2bfloat16(x - __bfloat162float(h));
        }
    }
}

// ---------------- MMA helpers --------------------------------------------------
__device__ __forceinline__ void ldsm_x4(uint32_t r[4], uint32_t addr) {
    asm volatile("ldmatrix.sync.aligned.m8n8.x4.shared.b16 {%0,%1,%2,%3}, [%4];\n"
        : "=r"(r[0]), "=r"(r[1]), "=r"(r[2]), "=r"(r[3]) : "r"(addr));
}
__device__ __forceinline__ void ldsm_x2t(uint32_t r[2], uint32_t addr) {
    asm volatile("ldmatrix.sync.aligned.m8n8.x2.trans.shared.b16 {%0,%1}, [%2];\n"
        : "=r"(r[0]), "=r"(r[1]) : "r"(addr));
}
__device__ __forceinline__ void mma16816(float* c, const uint32_t a[4], const uint32_t b[2]) {
    asm volatile(
        "mma.sync.aligned.m16n8k16.row.col.f32.bf16.bf16.f32 "
        "{%0,%1,%2,%3}, {%4,%5,%6,%7}, {%8,%9}, {%0,%1,%2,%3};\n"
        : "+f"(c[0]), "+f"(c[1]), "+f"(c[2]), "+f"(c[3])
        : "r"(a[0]), "r"(a[1]), "r"(a[2]), "r"(a[3]), "r"(b[0]), "r"(b[1]));
}

// ---------------- gates GEMM (128x128x32, 16 warps, 3-stage) ------------------
#define MM_SA 40
#define MM_SB 136
#define MM_BM 128
#define MM_BN 128
#define MM_BK 32
#define MM_ASZ (MM_BM*MM_SA)
#define MM_BSZ (MM_BK*MM_SB)
#define MM_STG (2*MM_ASZ + 2*MM_BSZ)   // 18944 elems
#define MM_NST 3
#define MM_SMEM (MM_NST*MM_STG*2)      // 113664 B

__global__ __launch_bounds__(512, 1) void mma_gemm_k(
    const __nv_bfloat16* __restrict__ Ahi, const __nv_bfloat16* __restrict__ Alo,
    const __nv_bfloat16* __restrict__ Bhi, const __nv_bfloat16* __restrict__ Blo,
    float* __restrict__ C, const int* __restrict__ msg, int t)
{
    extern __shared__ __nv_bfloat16 sm[];
    __nv_bfloat16* stg[MM_NST] = { sm, sm + MM_STG, sm + 2 * MM_STG };

    const int tid  = threadIdx.x;
    const int lane = tid & 31, warp = tid >> 5;
    const int bm = blockIdx.y * MM_BM, bn = blockIdx.x * MM_BN;
    const int wm = (warp >> 2) * 32, wn = (warp & 3) * 32;   // 32x32 warp tile

    float acc[2][4][4];
    #pragma unroll
    for (int i = 0; i < 2; i++)
        #pragma unroll
        for (int j = 0; j < 4; j++)
            #pragma unroll
            for (int l = 0; l < 4; l++) acc[i][j][l] = 0.f;

    auto issue_loads = [&](int s, int k0) {
        __nv_bfloat16* sAhi = stg[s];
        __nv_bfloat16* sAlo = stg[s] + MM_ASZ;
        __nv_bfloat16* sBhi = stg[s] + 2 * MM_ASZ;
        __nv_bfloat16* sBlo = stg[s] + 2 * MM_ASZ + MM_BSZ;
        int ar = tid >> 2, ac = (tid & 3) * 8;
        CP16(smem_u32(sAhi + ar * MM_SA + ac), Ahi + (size_t)(bm + ar) * XW + k0 + ac);
        CP16(smem_u32(sAlo + ar * MM_SA + ac), Alo + (size_t)(bm + ar) * XW + k0 + ac);
        int br = tid >> 4, bc = (tid & 15) * 8;
        CP16(smem_u32(sBhi + br * MM_SB + bc), Bhi + (size_t)(k0 + br) * G4 + bn + bc);
        CP16(smem_u32(sBlo + br * MM_SB + bc), Blo + (size_t)(k0 + br) * G4 + bn + bc);
        asm volatile("cp.async.commit_group;\n");
    };

    const int niter = XW / MM_BK;   // 24
    issue_loads(0, 0);
    issue_loads(1, MM_BK);

    const int a_ro = (lane & 7) + ((lane >> 3) & 1) * 8;
    const int a_ko = ((lane >> 4) & 1) * 8;
    const int b_ro = (lane & 7) + ((lane >> 3) & 1) * 8;

    for (int it = 0; it < niter; it++) {
        if (it + 2 < niter) { issue_loads((it + 2) % MM_NST, (it + 2) * MM_BK);
                              asm volatile("cp.async.wait_group 2;\n"); }
        else if (it + 1 < niter) asm volatile("cp.async.wait_group 1;\n");
        else                     asm volatile("cp.async.wait_group 0;\n");
        __syncthreads();

        const int s = it % MM_NST;
        const __nv_bfloat16* sAhi = stg[s];
        const __nv_bfloat16* sAlo = stg[s] + MM_ASZ;
        const __nv_bfloat16* sBhi = stg[s] + 2 * MM_ASZ;
        const __nv_bfloat16* sBlo = stg[s] + 2 * MM_ASZ + MM_BSZ;

        #pragma unroll
        for (int ks = 0; ks < MM_BK; ks += 16) {
            uint32_t bh[4][2], bl[4][2];
            #pragma unroll
            for (int nf = 0; nf < 4; nf++) {
                ldsm_x2t(bh[nf], smem_u32(sBhi + (ks + b_ro) * MM_SB + wn + nf * 8));
                ldsm_x2t(bl[nf], smem_u32(sBlo + (ks + b_ro) * MM_SB + wn + nf * 8));
            }
            uint32_t ah[2][4], al[2][4];
            #pragma unroll
            for (int mf = 0; mf < 2; mf++) {
                int arow = wm + mf * 16 + a_ro;
                ldsm_x4(ah[mf], smem_u32(sAhi + arow * MM_SA + ks + a_ko));
                ldsm_x4(al[mf], smem_u32(sAlo + arow * MM_SA + ks + a_ko));
            }
            #pragma unroll
            for (int mf = 0; mf < 2; mf++)
                #pragma unroll
                for (int nf = 0; nf < 4; nf++)
                    mma16816(acc[mf][nf], ah[mf], bh[nf]);
            #pragma unroll
            for (int mf = 0; mf < 2; mf++)
                #pragma unroll
                for (int nf = 0; nf < 4; nf++)
                    mma16816(acc[mf][nf], ah[mf], bl[nf]);
            #pragma unroll
            for (int mf = 0; mf < 2; mf++)
                #pragma unroll
                for (int nf = 0; nf < 4; nf++)
                    mma16816(acc[mf][nf], al[mf], bh[nf]);
        }
        __syncthreads();
    }

    // epilogue: GATT = acc + ProjEmb[tok] + BiasC
    #pragma unroll
    for (int mf = 0; mf < 2; mf++) {
        int row0 = bm + wm + mf * 16 + (lane >> 2);
        int tok0 = msg[row0 * TT + t];
        int tok1 = msg[(row0 + 8) * TT + t];
        const float* pe0 = g_ProjEmb + (size_t)tok0 * G4;
        const float* pe1 = g_ProjEmb + (size_t)tok1 * G4;
        #pragma unroll
        for (int nf = 0; nf < 4; nf++) {
            int col = bn + wn + nf * 8 + (lane & 3) * 2;
            float2 bi = *(const float2*)(g_BiasC + col);
            float2 p0 = *(const float2*)(pe0 + col);
            float2 p1 = *(const float2*)(pe1 + col);
            *(float2*)(C + (size_t)row0 * G4 + col) =
                make_float2((acc[mf][nf][0] + p0.x) + bi.x,
                            (acc[mf][nf][1] + p0.y) + bi.y);
            *(float2*)(C + (size_t)(row0 + 8) * G4 + col) =
                make_float2((acc[mf][nf][2] + p1.x) + bi.x,
                            (acc[mf][nf][3] + p1.y) + bi.y);
        }
    }
}

// ---------------- split-bf16 pq GEMM (64x64x32, 128 thr) ----------------------
#define P_SA 40
#define P_SB 72
#define P_BM 64
#define P_BN 64
#define P_BK 32
#define P_ASZ (P_BM*P_SA)
#define P_BSZ (P_BK*P_SB)
#define P_STG (2*P_ASZ + 2*P_BSZ)
#define P_SMEM (2*P_STG*2)

__global__ __launch_bounds__(128) void mma_pq_k(
    const __nv_bfloat16* __restrict__ Ahi, const __nv_bfloat16* __restrict__ Alo,
    const __nv_bfloat16* __restrict__ Bhi, const __nv_bfloat16* __restrict__ Blo,
    float* __restrict__ C, const float* __restrict__ bias,
    int M, int N, int K, int lda, int ldb, int ldc)
{
    extern __shared__ __nv_bfloat16 smb[];
    __nv_bfloat16* stg[2] = { smb, smb + P_STG };

    const int tid  = threadIdx.x;
    const int lane = tid & 31, warp = tid >> 5;
    const int bm = blockIdx.y * P_BM, bn = blockIdx.x * P_BN;
    const int wm = (warp >> 1) * 32, wn = (warp & 1) * 32;

    float acc[2][4][4];
    #pragma unroll
    for (int i = 0; i < 2; i++)
        #pragma unroll
        for (int j = 0; j < 4; j++)
            #pragma unroll
            for (int l = 0; l < 4; l++) acc[i][j][l] = 0.f;

    auto issue_loads = [&](int s, int k0) {
        __nv_bfloat16* sAhi = stg[s];
        __nv_bfloat16* sAlo = stg[s] + P_ASZ;
        __nv_bfloat16* sBhi = stg[s] + 2 * P_ASZ;
        __nv_bfloat16* sBlo = stg[s] + 2 * P_ASZ + P_BSZ;
        #pragma unroll
        for (int i = 0; i < 2; i++) {
            int ai = tid * 2 + i, ar = ai >> 2, ac = (ai & 3) * 8;
            CP16(smem_u32(sAhi + ar * P_SA + ac), Ahi + (size_t)(bm + ar) * lda + k0 + ac);
            CP16(smem_u32(sAlo + ar * P_SA + ac), Alo + (size_t)(bm + ar) * lda + k0 + ac);
            int bi = tid * 2 + i, br = bi >> 3, bc = (bi & 7) * 8;
            CP16(smem_u32(sBhi + br * P_SB + bc), Bhi + (size_t)(k0 + br) * ldb + bn + bc);
            CP16(smem_u32(sBlo + br * P_SB + bc), Blo + (size_t)(k0 + br) * ldb + bn + bc);
        }
        asm volatile("cp.async.commit_group;\n");
    };

    const int niter = K / P_BK;
    issue_loads(0, 0);

    const int a_ro = (lane & 7) + ((lane >> 3) & 1) * 8;
    const int a_ko = ((lane >> 4) & 1) * 8;
    const int b_ro = (lane & 7) + ((lane >> 3) & 1) * 8;

    for (int it = 0; it < niter; it++) {
        int s = it & 1;
        if (it + 1 < niter) { issue_loads(s ^ 1, (it + 1) * P_BK);
                              asm volatile("cp.async.wait_group 1;\n"); }
        else                  asm volatile("cp.async.wait_group 0;\n");
        __syncthreads();

        const __nv_bfloat16* sAhi = stg[s];
        const __nv_bfloat16* sAlo = stg[s] + P_ASZ;
        const __nv_bfloat16* sBhi = stg[s] + 2 * P_ASZ;
        const __nv_bfloat16* sBlo = stg[s] + 2 * P_ASZ + P_BSZ;

        #pragma unroll
        for (int ks = 0; ks < P_BK; ks += 16) {
            uint32_t bh[4][2], bl[4][2];
            #pragma unroll
            for (int nf = 0; nf < 4; nf++) {
                ldsm_x2t(bh[nf], smem_u32(sBhi + (ks + b_ro) * P_SB + wn + nf * 8));
                ldsm_x2t(bl[nf], smem_u32(sBlo + (ks + b_ro) * P_SB + wn + nf * 8));
            }
            uint32_t ah[2][4], al[2][4];
            #pragma unroll
            for (int mf = 0; mf < 2; mf++) {
                int arow = wm + mf * 16 + a_ro;
                ldsm_x4(ah[mf], smem_u32(sAhi + arow * P_SA + ks + a_ko));
                ldsm_x4(al[mf], smem_u32(sAlo + arow * P_SA + ks + a_ko));
            }
            #pragma unroll
            for (int mf = 0; mf < 2; mf++)
                #pragma unroll
                for (int nf = 0; nf < 4; nf++)
                    mma16816(acc[mf][nf], ah[mf], bh[nf]);
            #pragma unroll
            for (int mf = 0; mf < 2; mf++)
                #pragma unroll
                for (int nf = 0; nf < 4; nf++)
                    mma16816(acc[mf][nf], ah[mf], bl[nf]);
            #pragma unroll
            for (int mf = 0; mf < 2; mf++)
                #pragma unroll
                for (int nf = 0; nf < 4; nf++)
                    mma16816(acc[mf][nf], al[mf], bh[nf]);
        }
        __syncthreads();
    }

    #pragma unroll
    for (int mf = 0; mf < 2; mf++) {
        int row0 = bm + wm + mf * 16 + (lane >> 2);
        #pragma unroll
        for (int nf = 0; nf < 4; nf++) {
            int col = bn + wn + nf * 8 + (lane & 3) * 2;
            float b0 = bias[col], b1 = bias[col + 1];
            *(float2*)(C + (size_t)row0 * ldc + col) =
                make_float2(acc[mf][nf][0] + b0, acc[mf][nf][1] + b1);
            *(float2*)(C + (size_t)(row0 + 8) * ldc + col) =
                make_float2(acc[mf][nf][2] + b0, acc[mf][nf][3] + b1);
        }
    }
}

// ---------------- flash attend: 2-stage, issue-before-wait, warp0 softmax -----
#define FA_CH 8
#define FA_NCH (LL/FA_CH)
#define FA_SMEM ((2*FA_CH*EE + EE + LL + FA_CH + FA_CH + 8) * 4)

__global__ __launch_bounds__(256, 8) void attend_flash_k(
    const float* __restrict__ Mg, const int* __restrict__ mask,
    const int* __restrict__ lengths, float* __restrict__ out, int t)
{
    extern __shared__ float smf[];
    float* bufs[2] = { smf, smf + FA_CH * EE };
    float* smPQ   = smf + 2 * FA_CH * EE;
    float* smSall = smPQ + EE;
    float* smS8   = smSall + LL;
    float* smE    = smS8 + FA_CH;
    float* smMisc = smE + FA_CH;

    const int b = blockIdx.x, tid = threadIdx.x;
    const int warp = tid >> 5, lane = tid & 31;

    smPQ[tid] = g_PQ[b * EE + tid];
    const float* gM = Mg + (size_t)b * LL * EE;

    auto issue = [&](int c) {
        float* dst = bufs[c & 1];
        const float* src = gM + c * FA_CH * EE;
        #pragma unroll
        for (int i = 0; i < 2; i++) {
            int ch = tid + i * 256;
            CP16(smem_u32(dst + ch * 4), src + ch * 4);
        }
        asm volatile("cp.async.commit_group;\n");
    };

    issue(0);

    float a = 0.f;
    float m = -1e30f, d = 0.f;

    for (int c = 0; c < FA_NCH; c++) {
        if (c + 1 < FA_NCH) { issue(c + 1); asm volatile("cp.async.wait_group 1;\n"); }
        else                  asm volatile("cp.async.wait_group 0;\n");
        __syncthreads();
        float* smM = bufs[c & 1];

        {   // one row per warp (8 rows, 8 warps)
            int l = warp;
            float s = 0.f;
            #pragma unroll
            for (int j = 0; j < EE / 32; j++)
                s += smM[l * EE + lane + j * 32] * smPQ[lane + j * 32];
            #pragma unroll
            for (int o = 16; o; o >>= 1) s += __shfl_xor_sync(0xffffffffu, s, o);
            if (lane == 0) {
                int gl = c * FA_CH + l;
                float sv = (mask[b * LL + gl] != 0) ? -1e30f : s;
                smS8[l] = sv;
                smSall[gl] = sv;
            }
        }
        __syncthreads();

        if (warp == 0) {
            float sl = (lane < FA_CH) ? smS8[lane] : -1e30f;
            float mc = sl;
            #pragma unroll
            for (int o = 16; o; o >>= 1) mc = fmaxf(mc, __shfl_xor_sync(0xffffffffu, mc, o));
            float m_new = fmaxf(m, mc);
            float scale = expf(m - m_new);
            float e = (lane < FA_CH) ? expf(sl - m_new) : 0.f;
            float esum = e;
            #pragma unroll
            for (int o = 16; o; o >>= 1) esum += __shfl_xor_sync(0xffffffffu, esum, o);
            d = d * scale + esum;
            m = m_new;
            if (lane < FA_CH) smE[lane] = e;
            if (lane == 0) smMisc[0] = scale;
        }
        __syncthreads();

        float sc = smMisc[0];
        a *= sc;
        #pragma unroll
        for (int l = 0; l < FA_CH; l++)
            a += smE[l] * smM[l * EE + tid];
        __syncthreads();
    }

    if (warp == 0 && lane == 0) { smMisc[1] = m; smMisc[2] = 1.f / d; }
    __syncthreads();
    float m_fin = smMisc[1], inv_d = smMisc[2];

    float app = a * inv_d;
    __nv_bfloat16 h = __float2bfloat16(app);
    g_Xhi[(size_t)b * XW + tid] = h;
    g_Xlo[(size_t)b * XW + tid] = __float2bfloat16(app - __bfloat162float(h));

    if (tid < LL) {
        int len = lengths[b];
        len = min(max(len, 0), TT);
        if (len == t) out[(size_t)b * LL + tid] = expf(smSall[tid] - m_fin) * inv_d;
    }
}

// ---------------- LSTM cell (gates pre-summed in GATT) ------------------------
__global__ void lstm_k(int dummy)
{
    int idx = blockIdx.x * blockDim.x + threadIdx.x;
    int b = idx >> 9, j = idx & (HH - 1);
    const float* ga = g_GATT + (size_t)b * G4;
    float gi = ga[j];
    float gf = ga[HH + j];
    float gg = ga[2 * HH + j];
    float go = ga[3 * HH + j];
    float c  = g_C[idx];
    float si = 1.f / (1.f + expf(-gi));
    float sf = 1.f / (1.f + expf(-gf));
    float so = 1.f / (1.f + expf(-go));
    float cn = sf * c + si * tanhf(gg);
    float hn = so * tanhf(cn);
    g_C[idx] = cn;
    __nv_bfloat16 hb = __float2bfloat16(hn);
    g_Xhi[(size_t)b * XW + EE + j] = hb;
    g_Xlo[(size_t)b * XW + EE + j] = __float2bfloat16(hn - __bfloat162float(hb));
}

// ---------------- driver -----------------------------------------------------
extern "C" void kernel_launch(void* const* d_in, const int* in_sizes, int n_in,
                              void* d_out, int out_size)
{
    const int*   msg     = (const int*)d_in[0];
    const float* Mg      = (const float*)d_in[1];
    const int*   mask    = (const int*)d_in[2];
    const int*   lengths = (const int*)d_in[3];
    const float* emb     = (const float*)d_in[4];
    const float* Wq      = (const float*)d_in[5];
    const float* bq      = (const float*)d_in[6];
    const float* Wc      = (const float*)d_in[7];
    const float* bc      = (const float*)d_in[8];
    const float* W_ih    = (const float*)d_in[9];
    const float* W_hh    = (const float*)d_in[10];
    const float* b_ih    = (const float*)d_in[11];
    const float* b_hh    = (const float*)d_in[12];
    float* out = (float*)d_out;
    int Vp1 = in_sizes[4] / EE;
    if (Vp1 > VMAX) Vp1 = VMAX;
    int ntail = out_size - BSZ * LL;
    if (ntail < 0) ntail = 0;

    float *pPQ, *pGATT;
    __nv_bfloat16 *pXhi, *pXlo, *pWhi, *pWlo, *pWqThi, *pWqTlo;
    cudaGetSymbolAddress((void**)&pPQ,    g_PQ);
    cudaGetSymbolAddress((void**)&pGATT,  g_GATT);
    cudaGetSymbolAddress((void**)&pXhi,   g_Xhi);
    cudaGetSymbolAddress((void**)&pXlo,   g_Xlo);
    cudaGetSymbolAddress((void**)&pWhi,   g_Whi);
    cudaGetSymbolAddress((void**)&pWlo,   g_Wlo);
    cudaGetSymbolAddress((void**)&pWqThi, g_WqThi);
    cudaGetSymbolAddress((void**)&pWqTlo, g_WqTlo);

    cudaFuncSetAttribute(attend_flash_k, cudaFuncAttributeMaxDynamicSharedMemorySize, FA_SMEM);
    cudaFuncSetAttribute(mma_gemm_k, cudaFuncAttributeMaxDynamicSharedMemorySize, MM_SMEM);
    cudaFuncSetAttribute(mma_pq_k,   cudaFuncAttributeMaxDynamicSharedMemorySize, P_SMEM);

    // setup launches
    prep_k<<<dim3(24, 64, 5), dim3(32, 8)>>>(Wq, W_ih, Wc, W_hh,
                                             b_ih, b_hh, bc, bq, out, ntail);
    gemm2_k<<<dim3(32, 16, 1), 256>>>(emb, Vp1, 0);   // Wcomb split
    gemm2_k<<<dim3(32, 16, 2), 256>>>(emb, Vp1, 1);   // ProjEmb + WqT split

    for (int t = 0; t < TT; t++) {
        attend_flash_k<<<BSZ, 256, FA_SMEM>>>(Mg, mask, lengths, out, t);
        mma_gemm_k<<<dim3(G4 / MM_BN, BSZ / MM_BM), 512, MM_SMEM>>>(
            pXhi, pXlo, pWhi, pWlo, pGATT, msg, t);
        lstm_k<<<(BSZ * HH) / 256, 256>>>(0);
        mma_pq_k<<<dim3(EE / P_BN, BSZ / P_BM), 128, P_SMEM>>>(
            pXhi + EE, pXlo + EE, pWqThi, pWqTlo, pPQ, bq,
            BSZ, EE, HH, XW, EE, EE);
    }
    attend_flash_k<<<BSZ, 256, FA_SMEM>>>(Mg, mask, lengths, out, TT);
}